// round 14
// baseline (speedup 1.0000x reference)
#include <cuda_runtime.h>
#include <cuda_bf16.h>
#include <math.h>

#define HDIM 256
#define BSEG 4096
#define K1   (3 * HDIM)   // 768
#define SPLIT1 4          // gemm1 K-split (768 = 4 x 192)
#define SPLIT2 4          // gemm2 K-split (256 = 4 x 64)

#define POOL_GRID  1776   // 148 SMs x 12 resident 128-thread blocks
#define POOL_VBLKS (2 * BSEG)   // 8192 virtual work items (segment x col-half)

__device__ float g_combined[BSEG * K1];          // [B, 3H]
__device__ float g_part[SPLIT1 * BSEG * HDIM];   // split-K partials
__device__ float g_hidden[BSEG * HDIM];          // [B, H]

__device__ __forceinline__ int lower_bound_i32(const int* __restrict__ a,
                                               int n, int v) {
    int lo = 0, hi = n;
    while (lo < hi) {
        int mid = (lo + hi) >> 1;
        if (a[mid] < v) lo = mid + 1; else hi = mid;
    }
    return lo;
}

__device__ __forceinline__ void acc4(float4& s, float4& m, const float4 v) {
    s.x += v.x; s.y += v.y; s.z += v.z; s.w += v.w;
    m.x = fmaxf(m.x, v.x); m.y = fmaxf(m.y, v.y);
    m.z = fmaxf(m.z, v.z); m.w = fmaxf(m.w, v.w);
}

// ---------------------------------------------------------------------------
// Stage 1: persistent column-split segment pooling.
// Virtual item vb = 2*b + h: segment b, float4 columns [32h, 32h+32).
// 128 threads = 4 row-groups x 32 lanes; MLP=4; direct writes (no partials).
// Grid is exactly the resident-block count -> no wave quantization.
// ---------------------------------------------------------------------------
__global__ void __launch_bounds__(128)
pool_kernel(const float4* __restrict__ feat4,   // [N, 64] float4
            const int* __restrict__ batch,
            float4* __restrict__ combined4,     // [B, 192] float4 (mean|sum|max)
            int n_rows) {
    const int t = threadIdx.x;
    const int g = t >> 5;             // 0..3 row-group
    const int lane = t & 31;          // 0..31

    __shared__ int s_se[2];
    __shared__ float4 red_s[4][32];
    __shared__ float4 red_m[4][32];

    for (int vb = blockIdx.x; vb < POOL_VBLKS; vb += POOL_GRID) {
        const int b = vb >> 1;
        const int h = vb & 1;
        const int col = (h << 5) + lane;  // float4 column 0..63

        if (t < 2) s_se[t] = lower_bound_i32(batch, n_rows, b + t);
        __syncthreads();
        const int start = s_se[0];
        const int end   = s_se[1];
        const int cnt   = end - start;

        float4 s0 = make_float4(0.f, 0.f, 0.f, 0.f), s1 = s0;
        float4 m0 = make_float4(-INFINITY, -INFINITY, -INFINITY, -INFINITY);
        float4 m1 = m0;

        int i = start + g;
        for (; i + 12 < end; i += 16) {
            float4 v0 = __ldcs(&feat4[(size_t)(i +  0) * 64 + col]);
            float4 v1 = __ldcs(&feat4[(size_t)(i +  4) * 64 + col]);
            float4 v2 = __ldcs(&feat4[(size_t)(i +  8) * 64 + col]);
            float4 v3 = __ldcs(&feat4[(size_t)(i + 12) * 64 + col]);
            acc4(s0, m0, v0); acc4(s1, m1, v1);
            acc4(s0, m0, v2); acc4(s1, m1, v3);
        }
        for (; i < end; i += 4) {
            float4 v = __ldcs(&feat4[(size_t)i * 64 + col]);
            acc4(s0, m0, v);
        }
        float4 s = make_float4(s0.x + s1.x, s0.y + s1.y,
                               s0.z + s1.z, s0.w + s1.w);
        float4 m = make_float4(fmaxf(m0.x, m1.x), fmaxf(m0.y, m1.y),
                               fmaxf(m0.z, m1.z), fmaxf(m0.w, m1.w));

        red_s[g][lane] = s;
        red_m[g][lane] = m;
        __syncthreads();

        if (t < 32) {
            float4 S = red_s[0][t], M = red_m[0][t];
            #pragma unroll
            for (int gg = 1; gg < 4; ++gg) {
                float4 ps = red_s[gg][t], pm = red_m[gg][t];
                S.x += ps.x; S.y += ps.y; S.z += ps.z; S.w += ps.w;
                M.x = fmaxf(M.x, pm.x); M.y = fmaxf(M.y, pm.y);
                M.z = fmaxf(M.z, pm.z); M.w = fmaxf(M.w, pm.w);
            }
            float inv = (cnt > 0) ? (1.0f / (float)cnt) : 0.0f;
            if (cnt == 0) { S = make_float4(0.f, 0.f, 0.f, 0.f); M = S; }
            float4 mean = make_float4(S.x * inv, S.y * inv,
                                      S.z * inv, S.w * inv);
            const int L = (h << 5) + t;
            float4* row = combined4 + (size_t)b * 192;
            row[L]       = mean;
            row[64 + L]  = S;
            row[128 + L] = M;
        }
        __syncthreads();
    }
}

// ---------------------------------------------------------------------------
// Split-K GEMM (exact R7/R12 version — measured best; unchanged).
// BM=64, BN=64, BK=32, 256 threads, 4x4 f32x2 microtile.
// ---------------------------------------------------------------------------
__device__ __forceinline__ unsigned long long pack2(float x) {
    unsigned long long r;
    asm("mov.b64 %0, {%1, %1};" : "=l"(r) : "f"(x));
    return r;
}
#define FFMA2(acc, a, b) \
    asm("fma.rn.f32x2 %0, %1, %2, %0;" : "+l"(acc) : "l"(a), "l"(b))

__global__ void __launch_bounds__(256)
gemm_splitk(const float* __restrict__ A,
            const float* __restrict__ W,
            float* __restrict__ Cpart,
            int M, int K, int N, int k_chunk) {
    __shared__ float As[2][32][68];
    __shared__ float Bs[2][32][64];

    const int tid = threadIdx.x;
    const int tx  = tid & 15;
    const int ty  = tid >> 4;
    const int bm  = blockIdx.y * 64;
    const int bn  = blockIdx.x * 64;
    const int kb  = blockIdx.z * k_chunk;

    const int la0_r = tid >> 3,          la0_c = (tid & 7) * 4;
    const int la1_r = (tid + 256) >> 3,  la1_c = ((tid + 256) & 7) * 4;
    const int lb0_r = tid >> 4,          lb0_n = (tid & 15) * 4;
    const int lb1_r = (tid + 256) >> 4,  lb1_n = ((tid + 256) & 15) * 4;

    const int nk = k_chunk >> 5;
    float4 a0, a1, w0, w1;

    a0 = *(const float4*)&A[(size_t)(bm + la0_r) * K + kb + la0_c];
    a1 = *(const float4*)&A[(size_t)(bm + la1_r) * K + kb + la1_c];
    w0 = *(const float4*)&W[(size_t)(kb + lb0_r) * N + bn + lb0_n];
    w1 = *(const float4*)&W[(size_t)(kb + lb1_r) * N + bn + lb1_n];

    As[0][la0_c + 0][la0_r] = a0.x; As[0][la0_c + 1][la0_r] = a0.y;
    As[0][la0_c + 2][la0_r] = a0.z; As[0][la0_c + 3][la0_r] = a0.w;
    As[0][la1_c + 0][la1_r] = a1.x; As[0][la1_c + 1][la1_r] = a1.y;
    As[0][la1_c + 2][la1_r] = a1.z; As[0][la1_c + 3][la1_r] = a1.w;
    *(float4*)&Bs[0][lb0_r][lb0_n] = w0;
    *(float4*)&Bs[0][lb1_r][lb1_n] = w1;
    __syncthreads();

    unsigned long long acc2[4][2] = {};

    for (int kk = 0; kk < nk; ++kk) {
        const int buf = kk & 1;
        if (kk + 1 < nk) {
            const int k0 = kb + ((kk + 1) << 5);
            a0 = *(const float4*)&A[(size_t)(bm + la0_r) * K + k0 + la0_c];
            a1 = *(const float4*)&A[(size_t)(bm + la1_r) * K + k0 + la1_c];
            w0 = *(const float4*)&W[(size_t)(k0 + lb0_r) * N + bn + lb0_n];
            w1 = *(const float4*)&W[(size_t)(k0 + lb1_r) * N + bn + lb1_n];
        }

        #pragma unroll
        for (int k = 0; k < 32; ++k) {
            const float4 av = *(const float4*)&As[buf][k][ty * 4];
            const ulonglong2 bp = *(const ulonglong2*)&Bs[buf][k][tx * 4];
            const unsigned long long ap0 = pack2(av.x);
            const unsigned long long ap1 = pack2(av.y);
            const unsigned long long ap2 = pack2(av.z);
            const unsigned long long ap3 = pack2(av.w);
            FFMA2(acc2[0][0], ap0, bp.x); FFMA2(acc2[0][1], ap0, bp.y);
            FFMA2(acc2[1][0], ap1, bp.x); FFMA2(acc2[1][1], ap1, bp.y);
            FFMA2(acc2[2][0], ap2, bp.x); FFMA2(acc2[2][1], ap2, bp.y);
            FFMA2(acc2[3][0], ap3, bp.x); FFMA2(acc2[3][1], ap3, bp.y);
        }

        if (kk + 1 < nk) {
            const int nb = buf ^ 1;
            As[nb][la0_c + 0][la0_r] = a0.x; As[nb][la0_c + 1][la0_r] = a0.y;
            As[nb][la0_c + 2][la0_r] = a0.z; As[nb][la0_c + 3][la0_r] = a0.w;
            As[nb][la1_c + 0][la1_r] = a1.x; As[nb][la1_c + 1][la1_r] = a1.y;
            As[nb][la1_c + 2][la1_r] = a1.z; As[nb][la1_c + 3][la1_r] = a1.w;
            *(float4*)&Bs[nb][lb0_r][lb0_n] = w0;
            *(float4*)&Bs[nb][lb1_r][lb1_n] = w1;
            __syncthreads();
        }
    }

    float* Cp = Cpart + (size_t)blockIdx.z * M * N;
    #pragma unroll
    for (int iu = 0; iu < 4; ++iu) {
        const int m = bm + ty * 4 + iu;
        float x0, x1, x2, x3;
        asm("mov.b64 {%0, %1}, %2;" : "=f"(x0), "=f"(x1) : "l"(acc2[iu][0]));
        asm("mov.b64 {%0, %1}, %2;" : "=f"(x2), "=f"(x3) : "l"(acc2[iu][1]));
        *(float4*)&Cp[(size_t)m * N + bn + tx * 4] = make_float4(x0, x1, x2, x3);
    }
}

// ---------------------------------------------------------------------------
// Epilogue: 2 float4 per thread (MLP up to 8); sum parts + bias (+SiLU).
// ---------------------------------------------------------------------------
__global__ void __launch_bounds__(256)
epilogue(const float4* __restrict__ Cpart,
         const float4* __restrict__ bias4,
         float4* __restrict__ out4,
         int total4, int parts, int n4, int do_silu) {
    const int idx = (blockIdx.x * 256 + threadIdx.x) * 2;
    if (idx >= total4) return;

    float4 s0 = __ldcs(&Cpart[idx]);
    float4 s1 = __ldcs(&Cpart[idx + 1]);
    #pragma unroll 4
    for (int p = 1; p < parts; ++p) {
        const float4 v0 = __ldcs(&Cpart[(size_t)p * total4 + idx]);
        const float4 v1 = __ldcs(&Cpart[(size_t)p * total4 + idx + 1]);
        s0.x += v0.x; s0.y += v0.y; s0.z += v0.z; s0.w += v0.w;
        s1.x += v1.x; s1.y += v1.y; s1.z += v1.z; s1.w += v1.w;
    }
    const float4 b0 = bias4[idx & (n4 - 1)];
    const float4 b1 = bias4[(idx + 1) & (n4 - 1)];
    s0.x += b0.x; s0.y += b0.y; s0.z += b0.z; s0.w += b0.w;
    s1.x += b1.x; s1.y += b1.y; s1.z += b1.z; s1.w += b1.w;
    if (do_silu) {
        s0.x = s0.x / (1.0f + __expf(-s0.x));
        s0.y = s0.y / (1.0f + __expf(-s0.y));
        s0.z = s0.z / (1.0f + __expf(-s0.z));
        s0.w = s0.w / (1.0f + __expf(-s0.w));
        s1.x = s1.x / (1.0f + __expf(-s1.x));
        s1.y = s1.y / (1.0f + __expf(-s1.y));
        s1.z = s1.z / (1.0f + __expf(-s1.z));
        s1.w = s1.w / (1.0f + __expf(-s1.w));
    }
    out4[idx]     = s0;
    out4[idx + 1] = s1;
}

// ---------------------------------------------------------------------------
extern "C" void kernel_launch(void* const* d_in, const int* in_sizes, int n_in,
                              void* d_out, int out_size) {
    const float* feat  = (const float*)d_in[0];
    const int*   batch = (const int*)d_in[1];
    const float* W1    = (const float*)d_in[2];
    const float* b1    = (const float*)d_in[3];
    const float* W2    = (const float*)d_in[4];
    const float* b2    = (const float*)d_in[5];
    float*       out   = (float*)d_out;

    const int n_rows = in_sizes[1];

    float *combined, *part, *hidden;
    cudaGetSymbolAddress((void**)&combined, g_combined);
    cudaGetSymbolAddress((void**)&part,     g_part);
    cudaGetSymbolAddress((void**)&hidden,   g_hidden);

    pool_kernel<<<POOL_GRID, 128>>>((const float4*)feat, batch,
                                    (float4*)combined, n_rows);

    const int total4 = BSEG * HDIM / 4;           // 262144
    const int n4 = HDIM / 4;                      // 64
    const int epi_blocks = total4 / 2 / 256;      // 512

    dim3 g1(HDIM / 64, BSEG / 64, SPLIT1);        // (4, 64, 4) = 1024 CTAs
    gemm_splitk<<<g1, 256>>>(combined, W1, part, BSEG, K1, HDIM, K1 / SPLIT1);
    epilogue<<<epi_blocks, 256>>>((const float4*)part, (const float4*)b1,
                                  (float4*)hidden, total4, SPLIT1, n4, 1);

    dim3 g2(HDIM / 64, BSEG / 64, SPLIT2);        // (4, 64, 4) = 1024 CTAs
    gemm_splitk<<<g2, 256>>>(hidden, W2, part, BSEG, HDIM, HDIM, HDIM / SPLIT2);
    epilogue<<<epi_blocks, 256>>>((const float4*)part, (const float4*)b2,
                                  (float4*)out, total4, SPLIT2, n4, 0);
}

// round 15
// speedup vs baseline: 1.0337x; 1.0337x over previous
#include <cuda_runtime.h>
#include <cuda_bf16.h>
#include <math.h>

#define HDIM 256
#define BSEG 4096
#define K1   (3 * HDIM)   // 768
#define SPLIT1 4          // gemm1 K-split (768 = 4 x 192)
#define SPLIT2 4          // gemm2 K-split (256 = 4 x 64)
#define PSTRIDE (BSEG * HDIM)   // one split-K partial plane

__device__ float g_combined[BSEG * K1];           // [B, 3H]
__device__ float g_part1[SPLIT1 * BSEG * HDIM];   // gemm1 partials (16 MB)
__device__ float g_part2[SPLIT2 * BSEG * HDIM];   // gemm2 partials (16 MB)

__device__ __forceinline__ int lower_bound_i32(const int* __restrict__ a,
                                               int n, int v) {
    int lo = 0, hi = n;
    while (lo < hi) {
        int mid = (lo + hi) >> 1;
        if (a[mid] < v) lo = mid + 1; else hi = mid;
    }
    return lo;
}

__device__ __forceinline__ void acc4(float4& s, float4& m, const float4 v) {
    s.x += v.x; s.y += v.y; s.z += v.z; s.w += v.w;
    m.x = fmaxf(m.x, v.x); m.y = fmaxf(m.y, v.y);
    m.z = fmaxf(m.z, v.z); m.w = fmaxf(m.w, v.w);
}

// ---------------------------------------------------------------------------
// Stage 1: column-split segment pooling (exact R13 version — best measured).
// Block blk = 2*b + h: segment b, float4 columns [32h, 32h+32).
// ---------------------------------------------------------------------------
__global__ void __launch_bounds__(128)
pool_kernel(const float4* __restrict__ feat4,
            const int* __restrict__ batch,
            float4* __restrict__ combined4,
            int n_rows) {
    const int blk = blockIdx.x;
    const int b = blk >> 1;
    const int h = blk & 1;
    const int t = threadIdx.x;
    const int g = t >> 5;
    const int lane = t & 31;
    const int col = (h << 5) + lane;

    __shared__ int s_se[2];
    if (t < 2) s_se[t] = lower_bound_i32(batch, n_rows, b + t);
    __syncthreads();
    const int start = s_se[0];
    const int end   = s_se[1];
    const int cnt   = end - start;

    float4 s0 = make_float4(0.f, 0.f, 0.f, 0.f), s1 = s0;
    float4 m0 = make_float4(-INFINITY, -INFINITY, -INFINITY, -INFINITY);
    float4 m1 = m0;

    int i = start + g;
    for (; i + 12 < end; i += 16) {
        float4 v0 = __ldcs(&feat4[(size_t)(i +  0) * 64 + col]);
        float4 v1 = __ldcs(&feat4[(size_t)(i +  4) * 64 + col]);
        float4 v2 = __ldcs(&feat4[(size_t)(i +  8) * 64 + col]);
        float4 v3 = __ldcs(&feat4[(size_t)(i + 12) * 64 + col]);
        acc4(s0, m0, v0); acc4(s1, m1, v1);
        acc4(s0, m0, v2); acc4(s1, m1, v3);
    }
    for (; i < end; i += 4) {
        float4 v = __ldcs(&feat4[(size_t)i * 64 + col]);
        acc4(s0, m0, v);
    }
    float4 s = make_float4(s0.x + s1.x, s0.y + s1.y, s0.z + s1.z, s0.w + s1.w);
    float4 m = make_float4(fmaxf(m0.x, m1.x), fmaxf(m0.y, m1.y),
                           fmaxf(m0.z, m1.z), fmaxf(m0.w, m1.w));

    __shared__ float4 red_s[4][32];
    __shared__ float4 red_m[4][32];
    red_s[g][lane] = s;
    red_m[g][lane] = m;
    __syncthreads();

    if (t < 32) {
        float4 S = red_s[0][t], M = red_m[0][t];
        #pragma unroll
        for (int gg = 1; gg < 4; ++gg) {
            float4 ps = red_s[gg][t], pm = red_m[gg][t];
            S.x += ps.x; S.y += ps.y; S.z += ps.z; S.w += ps.w;
            M.x = fmaxf(M.x, pm.x); M.y = fmaxf(M.y, pm.y);
            M.z = fmaxf(M.z, pm.z); M.w = fmaxf(M.w, pm.w);
        }
        float inv = (cnt > 0) ? (1.0f / (float)cnt) : 0.0f;
        if (cnt == 0) { S = make_float4(0.f, 0.f, 0.f, 0.f); M = S; }
        float4 mean = make_float4(S.x * inv, S.y * inv, S.z * inv, S.w * inv);
        const int L = (h << 5) + t;
        float4* row = combined4 + (size_t)b * 192;
        row[L]       = mean;
        row[64 + L]  = S;
        row[128 + L] = M;
    }
}

// ---------------------------------------------------------------------------
// f32x2 helpers
// ---------------------------------------------------------------------------
__device__ __forceinline__ unsigned long long pack2(float x) {
    unsigned long long r;
    asm("mov.b64 %0, {%1, %1};" : "=l"(r) : "f"(x));
    return r;
}
#define FFMA2(acc, a, b) \
    asm("fma.rn.f32x2 %0, %1, %2, %0;" : "+l"(acc) : "l"(a), "l"(b))

__device__ __forceinline__ float silu1(float x) {
    return x / (1.0f + __expf(-x));
}

// ---------------------------------------------------------------------------
// GEMM1 split-K (exact R7/R12 kernel — unchanged).
// ---------------------------------------------------------------------------
__global__ void __launch_bounds__(256)
gemm_splitk(const float* __restrict__ A,
            const float* __restrict__ W,
            float* __restrict__ Cpart,
            int M, int K, int N, int k_chunk) {
    __shared__ float As[2][32][68];
    __shared__ float Bs[2][32][64];

    const int tid = threadIdx.x;
    const int tx  = tid & 15;
    const int ty  = tid >> 4;
    const int bm  = blockIdx.y * 64;
    const int bn  = blockIdx.x * 64;
    const int kb  = blockIdx.z * k_chunk;

    const int la0_r = tid >> 3,          la0_c = (tid & 7) * 4;
    const int la1_r = (tid + 256) >> 3,  la1_c = ((tid + 256) & 7) * 4;
    const int lb0_r = tid >> 4,          lb0_n = (tid & 15) * 4;
    const int lb1_r = (tid + 256) >> 4,  lb1_n = ((tid + 256) & 15) * 4;

    const int nk = k_chunk >> 5;
    float4 a0, a1, w0, w1;

    a0 = *(const float4*)&A[(size_t)(bm + la0_r) * K + kb + la0_c];
    a1 = *(const float4*)&A[(size_t)(bm + la1_r) * K + kb + la1_c];
    w0 = *(const float4*)&W[(size_t)(kb + lb0_r) * N + bn + lb0_n];
    w1 = *(const float4*)&W[(size_t)(kb + lb1_r) * N + bn + lb1_n];

    As[0][la0_c + 0][la0_r] = a0.x; As[0][la0_c + 1][la0_r] = a0.y;
    As[0][la0_c + 2][la0_r] = a0.z; As[0][la0_c + 3][la0_r] = a0.w;
    As[0][la1_c + 0][la1_r] = a1.x; As[0][la1_c + 1][la1_r] = a1.y;
    As[0][la1_c + 2][la1_r] = a1.z; As[0][la1_c + 3][la1_r] = a1.w;
    *(float4*)&Bs[0][lb0_r][lb0_n] = w0;
    *(float4*)&Bs[0][lb1_r][lb1_n] = w1;
    __syncthreads();

    unsigned long long acc2[4][2] = {};

    for (int kk = 0; kk < nk; ++kk) {
        const int buf = kk & 1;
        if (kk + 1 < nk) {
            const int k0 = kb + ((kk + 1) << 5);
            a0 = *(const float4*)&A[(size_t)(bm + la0_r) * K + k0 + la0_c];
            a1 = *(const float4*)&A[(size_t)(bm + la1_r) * K + k0 + la1_c];
            w0 = *(const float4*)&W[(size_t)(k0 + lb0_r) * N + bn + lb0_n];
            w1 = *(const float4*)&W[(size_t)(k0 + lb1_r) * N + bn + lb1_n];
        }

        #pragma unroll
        for (int k = 0; k < 32; ++k) {
            const float4 av = *(const float4*)&As[buf][k][ty * 4];
            const ulonglong2 bp = *(const ulonglong2*)&Bs[buf][k][tx * 4];
            const unsigned long long ap0 = pack2(av.x);
            const unsigned long long ap1 = pack2(av.y);
            const unsigned long long ap2 = pack2(av.z);
            const unsigned long long ap3 = pack2(av.w);
            FFMA2(acc2[0][0], ap0, bp.x); FFMA2(acc2[0][1], ap0, bp.y);
            FFMA2(acc2[1][0], ap1, bp.x); FFMA2(acc2[1][1], ap1, bp.y);
            FFMA2(acc2[2][0], ap2, bp.x); FFMA2(acc2[2][1], ap2, bp.y);
            FFMA2(acc2[3][0], ap3, bp.x); FFMA2(acc2[3][1], ap3, bp.y);
        }

        if (kk + 1 < nk) {
            const int nb = buf ^ 1;
            As[nb][la0_c + 0][la0_r] = a0.x; As[nb][la0_c + 1][la0_r] = a0.y;
            As[nb][la0_c + 2][la0_r] = a0.z; As[nb][la0_c + 3][la0_r] = a0.w;
            As[nb][la1_c + 0][la1_r] = a1.x; As[nb][la1_c + 1][la1_r] = a1.y;
            As[nb][la1_c + 2][la1_r] = a1.z; As[nb][la1_c + 3][la1_r] = a1.w;
            *(float4*)&Bs[nb][lb0_r][lb0_n] = w0;
            *(float4*)&Bs[nb][lb1_r][lb1_n] = w1;
            __syncthreads();
        }
    }

    float* Cp = Cpart + (size_t)blockIdx.z * M * N;
    #pragma unroll
    for (int iu = 0; iu < 4; ++iu) {
        const int m = bm + ty * 4 + iu;
        float x0, x1, x2, x3;
        asm("mov.b64 {%0, %1}, %2;" : "=f"(x0), "=f"(x1) : "l"(acc2[iu][0]));
        asm("mov.b64 {%0, %1}, %2;" : "=f"(x2), "=f"(x3) : "l"(acc2[iu][1]));
        *(float4*)&Cp[(size_t)m * N + bn + tx * 4] = make_float4(x0, x1, x2, x3);
    }
}

// ---------------------------------------------------------------------------
// GEMM2 with fused A: A[m][k] = silu(sum_p part1[p][m][k] + b1[k]).
// Same tile/microtile as gemm_splitk; only the A staging differs.
// ---------------------------------------------------------------------------
__device__ __forceinline__ float4 fused_hidden4(const float* __restrict__ P,
                                                size_t idx,
                                                const float4 bv) {
    float4 s = *(const float4*)&P[idx];
    #pragma unroll
    for (int p = 1; p < SPLIT1; ++p) {
        const float4 v = *(const float4*)&P[(size_t)p * PSTRIDE + idx];
        s.x += v.x; s.y += v.y; s.z += v.z; s.w += v.w;
    }
    s.x = silu1(s.x + bv.x); s.y = silu1(s.y + bv.y);
    s.z = silu1(s.z + bv.z); s.w = silu1(s.w + bv.w);
    return s;
}

__global__ void __launch_bounds__(256)
gemm2_fused(const float* __restrict__ P,      // gemm1 partials [SPLIT1][M][K]
            const float* __restrict__ b1,     // [K] bias of gemm1
            const float* __restrict__ W,
            float* __restrict__ Cpart,
            int M, int K, int N, int k_chunk) {
    __shared__ float As[2][32][68];
    __shared__ float Bs[2][32][64];

    const int tid = threadIdx.x;
    const int tx  = tid & 15;
    const int ty  = tid >> 4;
    const int bm  = blockIdx.y * 64;
    const int bn  = blockIdx.x * 64;
    const int kb  = blockIdx.z * k_chunk;

    const int la0_r = tid >> 3,          la0_c = (tid & 7) * 4;
    const int la1_r = (tid + 256) >> 3,  la1_c = ((tid + 256) & 7) * 4;
    const int lb0_r = tid >> 4,          lb0_n = (tid & 15) * 4;
    const int lb1_r = (tid + 256) >> 4,  lb1_n = ((tid + 256) & 15) * 4;

    const int nk = k_chunk >> 5;
    float4 a0, a1, w0, w1;

    {
        const float4 bv0 = *(const float4*)&b1[kb + la0_c];
        const float4 bv1 = *(const float4*)&b1[kb + la1_c];
        a0 = fused_hidden4(P, (size_t)(bm + la0_r) * K + kb + la0_c, bv0);
        a1 = fused_hidden4(P, (size_t)(bm + la1_r) * K + kb + la1_c, bv1);
    }
    w0 = *(const float4*)&W[(size_t)(kb + lb0_r) * N + bn + lb0_n];
    w1 = *(const float4*)&W[(size_t)(kb + lb1_r) * N + bn + lb1_n];

    As[0][la0_c + 0][la0_r] = a0.x; As[0][la0_c + 1][la0_r] = a0.y;
    As[0][la0_c + 2][la0_r] = a0.z; As[0][la0_c + 3][la0_r] = a0.w;
    As[0][la1_c + 0][la1_r] = a1.x; As[0][la1_c + 1][la1_r] = a1.y;
    As[0][la1_c + 2][la1_r] = a1.z; As[0][la1_c + 3][la1_r] = a1.w;
    *(float4*)&Bs[0][lb0_r][lb0_n] = w0;
    *(float4*)&Bs[0][lb1_r][lb1_n] = w1;
    __syncthreads();

    unsigned long long acc2[4][2] = {};

    for (int kk = 0; kk < nk; ++kk) {
        const int buf = kk & 1;
        if (kk + 1 < nk) {
            const int k0 = kb + ((kk + 1) << 5);
            const float4 bv0 = *(const float4*)&b1[k0 + la0_c];
            const float4 bv1 = *(const float4*)&b1[k0 + la1_c];
            a0 = fused_hidden4(P, (size_t)(bm + la0_r) * K + k0 + la0_c, bv0);
            a1 = fused_hidden4(P, (size_t)(bm + la1_r) * K + k0 + la1_c, bv1);
            w0 = *(const float4*)&W[(size_t)(k0 + lb0_r) * N + bn + lb0_n];
            w1 = *(const float4*)&W[(size_t)(k0 + lb1_r) * N + bn + lb1_n];
        }

        #pragma unroll
        for (int k = 0; k < 32; ++k) {
            const float4 av = *(const float4*)&As[buf][k][ty * 4];
            const ulonglong2 bp = *(const ulonglong2*)&Bs[buf][k][tx * 4];
            const unsigned long long ap0 = pack2(av.x);
            const unsigned long long ap1 = pack2(av.y);
            const unsigned long long ap2 = pack2(av.z);
            const unsigned long long ap3 = pack2(av.w);
            FFMA2(acc2[0][0], ap0, bp.x); FFMA2(acc2[0][1], ap0, bp.y);
            FFMA2(acc2[1][0], ap1, bp.x); FFMA2(acc2[1][1], ap1, bp.y);
            FFMA2(acc2[2][0], ap2, bp.x); FFMA2(acc2[2][1], ap2, bp.y);
            FFMA2(acc2[3][0], ap3, bp.x); FFMA2(acc2[3][1], ap3, bp.y);
        }

        if (kk + 1 < nk) {
            const int nb = buf ^ 1;
            As[nb][la0_c + 0][la0_r] = a0.x; As[nb][la0_c + 1][la0_r] = a0.y;
            As[nb][la0_c + 2][la0_r] = a0.z; As[nb][la0_c + 3][la0_r] = a0.w;
            As[nb][la1_c + 0][la1_r] = a1.x; As[nb][la1_c + 1][la1_r] = a1.y;
            As[nb][la1_c + 2][la1_r] = a1.z; As[nb][la1_c + 3][la1_r] = a1.w;
            *(float4*)&Bs[nb][lb0_r][lb0_n] = w0;
            *(float4*)&Bs[nb][lb1_r][lb1_n] = w1;
            __syncthreads();
        }
    }

    float* Cp = Cpart + (size_t)blockIdx.z * M * N;
    #pragma unroll
    for (int iu = 0; iu < 4; ++iu) {
        const int m = bm + ty * 4 + iu;
        float x0, x1, x2, x3;
        asm("mov.b64 {%0, %1}, %2;" : "=f"(x0), "=f"(x1) : "l"(acc2[iu][0]));
        asm("mov.b64 {%0, %1}, %2;" : "=f"(x2), "=f"(x3) : "l"(acc2[iu][1]));
        *(float4*)&Cp[(size_t)m * N + bn + tx * 4] = make_float4(x0, x1, x2, x3);
    }
}

// ---------------------------------------------------------------------------
// Final epilogue: out = sum parts + bias (no activation).
// ---------------------------------------------------------------------------
__global__ void __launch_bounds__(256)
epilogue(const float4* __restrict__ Cpart,
         const float4* __restrict__ bias4,
         float4* __restrict__ out4,
         int total4, int parts, int n4) {
    const int idx = (blockIdx.x * 256 + threadIdx.x) * 2;
    if (idx >= total4) return;

    float4 s0 = __ldcs(&Cpart[idx]);
    float4 s1 = __ldcs(&Cpart[idx + 1]);
    #pragma unroll 4
    for (int p = 1; p < parts; ++p) {
        const float4 v0 = __ldcs(&Cpart[(size_t)p * total4 + idx]);
        const float4 v1 = __ldcs(&Cpart[(size_t)p * total4 + idx + 1]);
        s0.x += v0.x; s0.y += v0.y; s0.z += v0.z; s0.w += v0.w;
        s1.x += v1.x; s1.y += v1.y; s1.z += v1.z; s1.w += v1.w;
    }
    const float4 b0 = bias4[idx & (n4 - 1)];
    const float4 b1v = bias4[(idx + 1) & (n4 - 1)];
    s0.x += b0.x; s0.y += b0.y; s0.z += b0.z; s0.w += b0.w;
    s1.x += b1v.x; s1.y += b1v.y; s1.z += b1v.z; s1.w += b1v.w;
    out4[idx]     = s0;
    out4[idx + 1] = s1;
}

// ---------------------------------------------------------------------------
extern "C" void kernel_launch(void* const* d_in, const int* in_sizes, int n_in,
                              void* d_out, int out_size) {
    const float* feat  = (const float*)d_in[0];
    const int*   batch = (const int*)d_in[1];
    const float* W1    = (const float*)d_in[2];
    const float* b1    = (const float*)d_in[3];
    const float* W2    = (const float*)d_in[4];
    const float* b2    = (const float*)d_in[5];
    float*       out   = (float*)d_out;

    const int n_rows = in_sizes[1];

    float *combined, *part1, *part2;
    cudaGetSymbolAddress((void**)&combined, g_combined);
    cudaGetSymbolAddress((void**)&part1,    g_part1);
    cudaGetSymbolAddress((void**)&part2,    g_part2);

    pool_kernel<<<2 * BSEG, 128>>>((const float4*)feat, batch,
                                   (float4*)combined, n_rows);

    const int total4 = BSEG * HDIM / 4;           // 262144
    const int n4 = HDIM / 4;                      // 64
    const int epi_blocks = total4 / 2 / 256;      // 512

    // GEMM1: combined [4096,768] @ W1 -> part1 (split-K 4)
    dim3 g1(HDIM / 64, BSEG / 64, SPLIT1);
    gemm_splitk<<<g1, 256>>>(combined, W1, part1, BSEG, K1, HDIM, K1 / SPLIT1);

    // GEMM2 (fused hidden): A = silu(sum part1 + b1), @ W2 -> part2 (split-K 4)
    dim3 g2(HDIM / 64, BSEG / 64, SPLIT2);
    gemm2_fused<<<g2, 256>>>(part1, b1, W2, part2,
                             BSEG, HDIM, HDIM, HDIM / SPLIT2);

    // Final: out = sum part2 + b2
    epilogue<<<epi_blocks, 256>>>((const float4*)part2, (const float4*)b2,
                                  (float4*)out, total4, SPLIT2, n4);
}

// round 16
// speedup vs baseline: 1.0694x; 1.0345x over previous
#include <cuda_runtime.h>
#include <cuda_bf16.h>
#include <mma.h>
#include <math.h>

using namespace nvcuda;

#define HDIM 256
#define BSEG 4096
#define K1   (3 * HDIM)   // 768

__device__ float g_combined[BSEG * K1];   // [B, 3H]
__device__ float g_hidden[BSEG * HDIM];   // [B, H]

__device__ __forceinline__ int lower_bound_i32(const int* __restrict__ a,
                                               int n, int v) {
    int lo = 0, hi = n;
    while (lo < hi) {
        int mid = (lo + hi) >> 1;
        if (a[mid] < v) lo = mid + 1; else hi = mid;
    }
    return lo;
}

__device__ __forceinline__ void acc4(float4& s, float4& m, const float4 v) {
    s.x += v.x; s.y += v.y; s.z += v.z; s.w += v.w;
    m.x = fmaxf(m.x, v.x); m.y = fmaxf(m.y, v.y);
    m.z = fmaxf(m.z, v.z); m.w = fmaxf(m.w, v.w);
}

// ---------------------------------------------------------------------------
// Stage 1: column-split segment pooling (exact R13 version — best measured).
// ---------------------------------------------------------------------------
__global__ void __launch_bounds__(128)
pool_kernel(const float4* __restrict__ feat4,
            const int* __restrict__ batch,
            float4* __restrict__ combined4,
            int n_rows) {
    const int blk = blockIdx.x;
    const int b = blk >> 1;
    const int h = blk & 1;
    const int t = threadIdx.x;
    const int g = t >> 5;
    const int lane = t & 31;
    const int col = (h << 5) + lane;

    __shared__ int s_se[2];
    if (t < 2) s_se[t] = lower_bound_i32(batch, n_rows, b + t);
    __syncthreads();
    const int start = s_se[0];
    const int end   = s_se[1];
    const int cnt   = end - start;

    float4 s0 = make_float4(0.f, 0.f, 0.f, 0.f), s1 = s0;
    float4 m0 = make_float4(-INFINITY, -INFINITY, -INFINITY, -INFINITY);
    float4 m1 = m0;

    int i = start + g;
    for (; i + 12 < end; i += 16) {
        float4 v0 = __ldcs(&feat4[(size_t)(i +  0) * 64 + col]);
        float4 v1 = __ldcs(&feat4[(size_t)(i +  4) * 64 + col]);
        float4 v2 = __ldcs(&feat4[(size_t)(i +  8) * 64 + col]);
        float4 v3 = __ldcs(&feat4[(size_t)(i + 12) * 64 + col]);
        acc4(s0, m0, v0); acc4(s1, m1, v1);
        acc4(s0, m0, v2); acc4(s1, m1, v3);
    }
    for (; i < end; i += 4) {
        float4 v = __ldcs(&feat4[(size_t)i * 64 + col]);
        acc4(s0, m0, v);
    }
    float4 s = make_float4(s0.x + s1.x, s0.y + s1.y, s0.z + s1.z, s0.w + s1.w);
    float4 m = make_float4(fmaxf(m0.x, m1.x), fmaxf(m0.y, m1.y),
                           fmaxf(m0.z, m1.z), fmaxf(m0.w, m1.w));

    __shared__ float4 red_s[4][32];
    __shared__ float4 red_m[4][32];
    red_s[g][lane] = s;
    red_m[g][lane] = m;
    __syncthreads();

    if (t < 32) {
        float4 S = red_s[0][t], M = red_m[0][t];
        #pragma unroll
        for (int gg = 1; gg < 4; ++gg) {
            float4 ps = red_s[gg][t], pm = red_m[gg][t];
            S.x += ps.x; S.y += ps.y; S.z += ps.z; S.w += ps.w;
            M.x = fmaxf(M.x, pm.x); M.y = fmaxf(M.y, pm.y);
            M.z = fmaxf(M.z, pm.z); M.w = fmaxf(M.w, pm.w);
        }
        float inv = (cnt > 0) ? (1.0f / (float)cnt) : 0.0f;
        if (cnt == 0) { S = make_float4(0.f, 0.f, 0.f, 0.f); M = S; }
        float4 mean = make_float4(S.x * inv, S.y * inv, S.z * inv, S.w * inv);
        const int L = (h << 5) + t;
        float4* row = combined4 + (size_t)b * 192;
        row[L]       = mean;
        row[64 + L]  = S;
        row[128 + L] = M;
    }
}

// ---------------------------------------------------------------------------
// tf32 tensor-core GEMM: C[M,N] = act(A[M,K] @ W[K,N] + bias).
// BM=32, BN=64, BK=16, 128 threads (4 warps), wmma m16n16k8.
// Warp w: m-half wm = w&1 (16 rows), n-half wn = w>>1 (32 cols = 2 frags).
// Accumulators staged through smem for a coalesced bias/SiLU epilogue.
// ---------------------------------------------------------------------------
#define LDA 24   // 24*4 = 96 B row stride (16B-aligned), mult of 4
#define LDB 68   // 68*4 = 272 B (16B-aligned)
#define LDC 68

__global__ void __launch_bounds__(128)
gemm_tc(const float* __restrict__ A,
        const float* __restrict__ W,
        const float* __restrict__ bias,
        float* __restrict__ C,
        int M, int K, int N, int do_silu) {
    __shared__ float As[32][LDA];
    __shared__ float Bs[16][LDB];
    __shared__ float Cs[32][LDC];

    const int tid = threadIdx.x;
    const int warp = tid >> 5;
    const int bm = blockIdx.y * 32;
    const int bn = blockIdx.x * 64;
    const int wm = (warp & 1) * 16;   // warp row offset
    const int wn = (warp >> 1) * 32;  // warp col offset

    wmma::fragment<wmma::accumulator, 16, 16, 8, float> c0, c1;
    wmma::fill_fragment(c0, 0.0f);
    wmma::fill_fragment(c1, 0.0f);

    // A tile load indices: 32x16 = 128 float4, 1/thread
    const int ar = tid >> 2, ac = (tid & 3) * 4;
    // B tile load indices: 16x64 = 256 float4, 2/thread
    const int br = tid >> 4, bc = (tid & 15) * 4;

    for (int k0 = 0; k0 < K; k0 += 16) {
        *(float4*)&As[ar][ac] =
            *(const float4*)&A[(size_t)(bm + ar) * K + k0 + ac];
        *(float4*)&Bs[br][bc] =
            *(const float4*)&W[(size_t)(k0 + br) * N + bn + bc];
        *(float4*)&Bs[br + 8][bc] =
            *(const float4*)&W[(size_t)(k0 + br + 8) * N + bn + bc];
        __syncthreads();

        #pragma unroll
        for (int ks = 0; ks < 16; ks += 8) {
            wmma::fragment<wmma::matrix_a, 16, 16, 8,
                           wmma::precision::tf32, wmma::row_major> a;
            wmma::fragment<wmma::matrix_b, 16, 16, 8,
                           wmma::precision::tf32, wmma::row_major> b0, b1;
            wmma::load_matrix_sync(a, &As[wm][ks], LDA);
            wmma::load_matrix_sync(b0, &Bs[ks][wn], LDB);
            wmma::load_matrix_sync(b1, &Bs[ks][wn + 16], LDB);
            #pragma unroll
            for (int i = 0; i < a.num_elements; ++i)
                a.x[i] = wmma::__float_to_tf32(a.x[i]);
            #pragma unroll
            for (int i = 0; i < b0.num_elements; ++i) {
                b0.x[i] = wmma::__float_to_tf32(b0.x[i]);
                b1.x[i] = wmma::__float_to_tf32(b1.x[i]);
            }
            wmma::mma_sync(c0, a, b0, c0);
            wmma::mma_sync(c1, a, b1, c1);
        }
        __syncthreads();
    }

    wmma::store_matrix_sync(&Cs[wm][wn],      c0, LDC, wmma::mem_row_major);
    wmma::store_matrix_sync(&Cs[wm][wn + 16], c1, LDC, wmma::mem_row_major);
    __syncthreads();

    const int er = tid >> 4;            // 0..7
    const int ec = (tid & 15) * 4;      // 0..60
    const float4 bv = *(const float4*)&bias[bn + ec];
    #pragma unroll
    for (int i = 0; i < 4; ++i) {
        const int row = i * 8 + er;
        float4 v = *(float4*)&Cs[row][ec];
        v.x += bv.x; v.y += bv.y; v.z += bv.z; v.w += bv.w;
        if (do_silu) {
            v.x = v.x / (1.0f + __expf(-v.x));
            v.y = v.y / (1.0f + __expf(-v.y));
            v.z = v.z / (1.0f + __expf(-v.z));
            v.w = v.w / (1.0f + __expf(-v.w));
        }
        *(float4*)&C[(size_t)(bm + row) * N + bn + ec] = v;
    }
}

// ---------------------------------------------------------------------------
extern "C" void kernel_launch(void* const* d_in, const int* in_sizes, int n_in,
                              void* d_out, int out_size) {
    const float* feat  = (const float*)d_in[0];
    const int*   batch = (const int*)d_in[1];
    const float* W1    = (const float*)d_in[2];
    const float* b1    = (const float*)d_in[3];
    const float* W2    = (const float*)d_in[4];
    const float* b2    = (const float*)d_in[5];
    float*       out   = (float*)d_out;

    const int n_rows = in_sizes[1];

    float *combined, *hidden;
    cudaGetSymbolAddress((void**)&combined, g_combined);
    cudaGetSymbolAddress((void**)&hidden,   g_hidden);

    pool_kernel<<<2 * BSEG, 128>>>((const float4*)feat, batch,
                                   (float4*)combined, n_rows);

    dim3 g1(HDIM / 64, BSEG / 32);   // (4, 128) = 512 CTAs
    gemm_tc<<<g1, 128>>>(combined, W1, b1, hidden, BSEG, K1, HDIM, 1);

    dim3 g2(HDIM / 64, BSEG / 32);
    gemm_tc<<<g2, 128>>>(hidden, W2, b2, out, BSEG, HDIM, HDIM, 0);
}

// round 17
// speedup vs baseline: 1.0924x; 1.0215x over previous
#include <cuda_runtime.h>
#include <cuda_bf16.h>
#include <mma.h>
#include <math.h>

using namespace nvcuda;

#define HDIM 256
#define BSEG 4096
#define K1   (3 * HDIM)   // 768

__device__ float g_combined[BSEG * K1];   // [B, 3H]
__device__ float g_hidden[BSEG * HDIM];   // [B, H]

__device__ __forceinline__ int lower_bound_i32(const int* __restrict__ a,
                                               int n, int v) {
    int lo = 0, hi = n;
    while (lo < hi) {
        int mid = (lo + hi) >> 1;
        if (a[mid] < v) lo = mid + 1; else hi = mid;
    }
    return lo;
}

__device__ __forceinline__ void acc4(float4& s, float4& m, const float4 v) {
    s.x += v.x; s.y += v.y; s.z += v.z; s.w += v.w;
    m.x = fmaxf(m.x, v.x); m.y = fmaxf(m.y, v.y);
    m.z = fmaxf(m.z, v.z); m.w = fmaxf(m.w, v.w);
}

// ---------------------------------------------------------------------------
// Stage 1: column-split segment pooling (exact R13/R16 version).
// ---------------------------------------------------------------------------
__global__ void __launch_bounds__(128)
pool_kernel(const float4* __restrict__ feat4,
            const int* __restrict__ batch,
            float4* __restrict__ combined4,
            int n_rows) {
    const int blk = blockIdx.x;
    const int b = blk >> 1;
    const int h = blk & 1;
    const int t = threadIdx.x;
    const int g = t >> 5;
    const int lane = t & 31;
    const int col = (h << 5) + lane;

    __shared__ int s_se[2];
    if (t < 2) s_se[t] = lower_bound_i32(batch, n_rows, b + t);
    __syncthreads();
    const int start = s_se[0];
    const int end   = s_se[1];
    const int cnt   = end - start;

    float4 s0 = make_float4(0.f, 0.f, 0.f, 0.f), s1 = s0;
    float4 m0 = make_float4(-INFINITY, -INFINITY, -INFINITY, -INFINITY);
    float4 m1 = m0;

    int i = start + g;
    for (; i + 12 < end; i += 16) {
        float4 v0 = __ldcs(&feat4[(size_t)(i +  0) * 64 + col]);
        float4 v1 = __ldcs(&feat4[(size_t)(i +  4) * 64 + col]);
        float4 v2 = __ldcs(&feat4[(size_t)(i +  8) * 64 + col]);
        float4 v3 = __ldcs(&feat4[(size_t)(i + 12) * 64 + col]);
        acc4(s0, m0, v0); acc4(s1, m1, v1);
        acc4(s0, m0, v2); acc4(s1, m1, v3);
    }
    for (; i < end; i += 4) {
        float4 v = __ldcs(&feat4[(size_t)i * 64 + col]);
        acc4(s0, m0, v);
    }
    float4 s = make_float4(s0.x + s1.x, s0.y + s1.y, s0.z + s1.z, s0.w + s1.w);
    float4 m = make_float4(fmaxf(m0.x, m1.x), fmaxf(m0.y, m1.y),
                           fmaxf(m0.z, m1.z), fmaxf(m0.w, m1.w));

    __shared__ float4 red_s[4][32];
    __shared__ float4 red_m[4][32];
    red_s[g][lane] = s;
    red_m[g][lane] = m;
    __syncthreads();

    if (t < 32) {
        float4 S = red_s[0][t], M = red_m[0][t];
        #pragma unroll
        for (int gg = 1; gg < 4; ++gg) {
            float4 ps = red_s[gg][t], pm = red_m[gg][t];
            S.x += ps.x; S.y += ps.y; S.z += ps.z; S.w += ps.w;
            M.x = fmaxf(M.x, pm.x); M.y = fmaxf(M.y, pm.y);
            M.z = fmaxf(M.z, pm.z); M.w = fmaxf(M.w, pm.w);
        }
        float inv = (cnt > 0) ? (1.0f / (float)cnt) : 0.0f;
        if (cnt == 0) { S = make_float4(0.f, 0.f, 0.f, 0.f); M = S; }
        float4 mean = make_float4(S.x * inv, S.y * inv, S.z * inv, S.w * inv);
        const int L = (h << 5) + t;
        float4* row = combined4 + (size_t)b * 192;
        row[L]       = mean;
        row[64 + L]  = S;
        row[128 + L] = M;
    }
}

// ---------------------------------------------------------------------------
// tf32 tensor-core GEMM v2: BM=64, BN=64, BK=16, 256 threads (8 warps),
// double-buffered smem, tf32 conversion at staging (clean inner loop).
// Warp (2 cols x 4 rows): wm = (warp>>1)*16, wn = (warp&1)*32; 2 c frags.
// ---------------------------------------------------------------------------
#define LDA 20   // 16 + 4 pad; 20*4 = 80 B (16B multiple)
#define LDB 68   // 64 + 4 pad; 272 B (16B multiple)
#define LDC 68

__device__ __forceinline__ float4 cvt_tf32_4(float4 v) {
    v.x = wmma::__float_to_tf32(v.x);
    v.y = wmma::__float_to_tf32(v.y);
    v.z = wmma::__float_to_tf32(v.z);
    v.w = wmma::__float_to_tf32(v.w);
    return v;
}

__global__ void __launch_bounds__(256)
gemm_tc(const float* __restrict__ A,
        const float* __restrict__ W,
        const float* __restrict__ bias,
        float* __restrict__ C,
        int M, int K, int N, int do_silu) {
    __shared__ float As[2][64][LDA];
    __shared__ float Bs[2][16][LDB];
    __shared__ float Cs[64][LDC];

    const int tid  = threadIdx.x;
    const int warp = tid >> 5;
    const int bm = blockIdx.y * 64;
    const int bn = blockIdx.x * 64;
    const int wm = (warp >> 1) * 16;
    const int wn = (warp & 1) * 32;

    wmma::fragment<wmma::accumulator, 16, 16, 8, float> c0, c1;
    wmma::fill_fragment(c0, 0.0f);
    wmma::fill_fragment(c1, 0.0f);

    // A tile 64x16 = 256 float4 (1/thread); B tile 16x64 = 256 float4 (1/thread)
    const int ar = tid >> 2, ac = (tid & 3) * 4;
    const int br = tid >> 4, bc = (tid & 15) * 4;

    const int nk = K >> 4;
    float4 a4, b4;

    a4 = cvt_tf32_4(*(const float4*)&A[(size_t)(bm + ar) * K + ac]);
    b4 = cvt_tf32_4(*(const float4*)&W[(size_t)br * N + bn + bc]);
    *(float4*)&As[0][ar][ac] = a4;
    *(float4*)&Bs[0][br][bc] = b4;
    __syncthreads();

    for (int kk = 0; kk < nk; ++kk) {
        const int buf = kk & 1;
        if (kk + 1 < nk) {
            const int k0 = (kk + 1) << 4;
            a4 = cvt_tf32_4(*(const float4*)&A[(size_t)(bm + ar) * K + k0 + ac]);
            b4 = cvt_tf32_4(*(const float4*)&W[(size_t)(k0 + br) * N + bn + bc]);
        }

        #pragma unroll
        for (int ks = 0; ks < 16; ks += 8) {
            wmma::fragment<wmma::matrix_a, 16, 16, 8,
                           wmma::precision::tf32, wmma::row_major> a;
            wmma::fragment<wmma::matrix_b, 16, 16, 8,
                           wmma::precision::tf32, wmma::row_major> b0, b1;
            wmma::load_matrix_sync(a, &As[buf][wm][ks], LDA);
            wmma::load_matrix_sync(b0, &Bs[buf][ks][wn], LDB);
            wmma::load_matrix_sync(b1, &Bs[buf][ks][wn + 16], LDB);
            wmma::mma_sync(c0, a, b0, c0);
            wmma::mma_sync(c1, a, b1, c1);
        }

        if (kk + 1 < nk) {
            const int nb = buf ^ 1;
            *(float4*)&As[nb][ar][ac] = a4;
            *(float4*)&Bs[nb][br][bc] = b4;
            __syncthreads();
        }
    }

    wmma::store_matrix_sync(&Cs[wm][wn],      c0, LDC, wmma::mem_row_major);
    wmma::store_matrix_sync(&Cs[wm][wn + 16], c1, LDC, wmma::mem_row_major);
    __syncthreads();

    // Epilogue: 64x64 tile, 256 threads -> 4 rows of 16 float4 each
    const int er = tid >> 4;            // 0..15
    const int ec = (tid & 15) * 4;      // 0..60
    const float4 bv = *(const float4*)&bias[bn + ec];
    #pragma unroll
    for (int i = 0; i < 4; ++i) {
        const int row = i * 16 + er;
        float4 v = *(float4*)&Cs[row][ec];
        v.x += bv.x; v.y += bv.y; v.z += bv.z; v.w += bv.w;
        if (do_silu) {
            v.x = v.x / (1.0f + __expf(-v.x));
            v.y = v.y / (1.0f + __expf(-v.y));
            v.z = v.z / (1.0f + __expf(-v.z));
            v.w = v.w / (1.0f + __expf(-v.w));
        }
        *(float4*)&C[(size_t)(bm + row) * N + bn + ec] = v;
    }
}

// ---------------------------------------------------------------------------
extern "C" void kernel_launch(void* const* d_in, const int* in_sizes, int n_in,
                              void* d_out, int out_size) {
    const float* feat  = (const float*)d_in[0];
    const int*   batch = (const int*)d_in[1];
    const float* W1    = (const float*)d_in[2];
    const float* b1    = (const float*)d_in[3];
    const float* W2    = (const float*)d_in[4];
    const float* b2    = (const float*)d_in[5];
    float*       out   = (float*)d_out;

    const int n_rows = in_sizes[1];

    float *combined, *hidden;
    cudaGetSymbolAddress((void**)&combined, g_combined);
    cudaGetSymbolAddress((void**)&hidden,   g_hidden);

    pool_kernel<<<2 * BSEG, 128>>>((const float4*)feat, batch,
                                   (float4*)combined, n_rows);

    dim3 g1(HDIM / 64, BSEG / 64);   // (4, 64) = 256 CTAs
    gemm_tc<<<g1, 256>>>(combined, W1, b1, hidden, BSEG, K1, HDIM, 1);

    dim3 g2(HDIM / 64, BSEG / 64);
    gemm_tc<<<g2, 256>>>(hidden, W2, b2, out, BSEG, HDIM, HDIM, 0);
}